// round 12
// baseline (speedup 1.0000x reference)
#include <cuda_runtime.h>

// NeighborlistForInference: brute-force N^2 upper-triangular pair list.
//
// Output layout (fp32, 6*P elements, P = n(n-1)/2):
//   [0   ,  P) : i index per pair (-1 if out of cutoff)
//   [P   , 2P) : j index per pair (-1)
//   [2P  , 3P) : d_ij (0)
//   [3P  , 6P) : r_ij row-major [P,3] (0)
//
// Round-11 = R10 + fast-path issue surgery:
//  * warp-constant output (768B) written by ONE predicated st.global.cs.v8.f32
//    on lanes 0..23 (32B/lane, Blackwell 256-bit stores): lanes 0-3 -> i block,
//    4-7 -> j block, 8-11 -> d block, 12-23 -> r block. Pointer/value/stride
//    per lane hoisted to the prologue.
//  * (float)i / (float)j conversions moved into the rare slow path.
//  * hot-loop loads clamped (min(j, n-1)) instead of predicated; partial
//    iterations always take the guarded scalar path (full == false).
//  * mask via s <= 0x3E800001 == (IEEE sqrtf(s) <= 0.5f); slow path stores
//    bit-identical values to R6/R10 (rel_err 3e-8).

#ifndef NL_CUTOFF
#define NL_CUTOFF 0.5f
#endif

#define BLOCK_THREADS 256   // 8 warps * 128 pairs = 1024 pairs per block

__device__ __forceinline__ int tri_start(int i, int n) {
    return (i * (2 * n - i - 1)) >> 1;     // row start, max ~36M fits int32
}

__device__ __forceinline__ int tri_row(int p, int n) {
    const int a = 2 * n - 1;
    const int disc = a * a - 8 * p;
    int i = (int)(0.5f * ((float)a - sqrtf((float)disc)));
    if (i < 0) i = 0;
    if (i > n - 2) i = n - 2;
    while (p < tri_start(i, n)) --i;
    while (i < n - 2 && p >= tri_start(i + 1, n)) ++i;
    return i;
}

__global__ __launch_bounds__(BLOCK_THREADS)
void neighborlist_kernel(const float* __restrict__ pos,
                         const float* __restrict__ box,
                         const int*   __restrict__ is_periodic,
                         float* __restrict__ out_i,
                         float* __restrict__ out_j,
                         float* __restrict__ out_d,
                         float* __restrict__ out_r,
                         int n, int P)
{
    const int warp = (blockIdx.x * BLOCK_THREADS + threadIdx.x) >> 5;
    const int lane = threadIdx.x & 31;
    const int wb   = warp * 128;
    if (wb >= P) return;

    // ---- per-lane triangular index at first pair (clamped for tail lanes)
    int p  = wb + lane;
    const int pc = min(p, P - 1);
    int i  = tri_row(pc, n);
    int rs = tri_start(i, n);
    int j  = i + 1 + (pc - rs);

    const float Lx = box[0], Ly = box[4], Lz = box[8];
    const float hx = 0.5f * Lx, hy = 0.5f * Ly, hz = 0.5f * Lz;
    const int per = *is_periodic;

    // largest float s with fl(sqrt(s)) <= 0.5  (== cutoff^2 + 1 ulp)
    const float SMAX = __uint_as_float(0x3E800001u);

    float xi = pos[3 * i + 0], yi = pos[3 * i + 1], zi = pos[3 * i + 2];

    // ---- fast-path cooperative store plan: lanes 0..23, 32B (8 floats) each.
    //   lanes 0-3: i block   (wb + 8*lane)        stride 32 floats/iter
    //   lanes 4-7: j block                        stride 32
    //   lanes 8-11: d block                       stride 32
    //   lanes 12-23: r block (3*wb + 8*(lane-12)) stride 96
    float* fast_ptr;
    {
        float* sb = (lane < 4) ? out_i : (lane < 8) ? out_j
                  : (lane < 12) ? out_d : out_r;
        const int off = (lane < 12) ? (wb + 8 * (lane & 3))
                                    : (3 * wb + 8 * (lane - 12));
        fast_ptr = sb + off;
    }
    const int   fast_stride = (lane < 12) ? 32 : 96;
    const float fast_val    = (lane < 8) ? -1.0f : 0.0f;

    #pragma unroll
    for (int m = 0; m < 4; ++m) {
        const int pb = wb + 32 * m;
        if (pb >= P) break;
        if (m) {
            p += 32;
            j += 32;
            if (j >= n && p < P) {             // row crossing(s)
                do {
                    rs += n - 1 - i;
                    ++i;
                    j = i + 1 + (p - rs);
                } while (j >= n);
                xi = pos[3 * i + 0]; yi = pos[3 * i + 1]; zi = pos[3 * i + 2];
            }
        }

        // memory-safe load index (tail lanes may have walked past n-1)
        const int jc = min(j, n - 1);
        float dx = xi - pos[3 * jc + 0];
        float dy = yi - pos[3 * jc + 1];
        float dz = zi - pos[3 * jc + 2];
        if (per) {
            // exact minimum-image for r in (-L, L): t in (-L/2, 3L/2)
            float tx = dx + hx; tx = (tx >= Lx) ? tx - Lx : tx; tx = (tx < 0.0f) ? tx + Lx : tx; dx = tx - hx;
            float ty = dy + hy; ty = (ty >= Ly) ? ty - Ly : ty; ty = (ty < 0.0f) ? ty + Ly : ty; dy = ty - hy;
            float tz = dz + hz; tz = (tz >= Lz) ? tz - Lz : tz; tz = (tz < 0.0f) ? tz + Lz : tz; dz = tz - hz;
        }
        const float s  = dx * dx + dy * dy + dz * dz;   // same contraction as R6
        const bool  in = (s <= SMAX);                   // == (sqrtf(s) <= 0.5f)
        const bool  full = (pb + 32 <= P);

        if (full && !__any_sync(0xffffffffu, in)) {
            // all 32 pairs out of cutoff: one 256-bit store on lanes 0..23
            if (lane < 24) {
                asm volatile(
                    "st.global.cs.v8.f32 [%0], {%1,%2,%3,%4,%5,%6,%7,%8};"
                    :: "l"(fast_ptr),
                       "f"(fast_val), "f"(fast_val), "f"(fast_val), "f"(fast_val),
                       "f"(fast_val), "f"(fast_val), "f"(fast_val), "f"(fast_val)
                    : "memory");
            }
        } else if (p < P) {
            const float d    = sqrtf(s);        // IEEE; rare path
            const float fi_f = (float)i;
            const float fj_f = (float)j;
            __stcs(out_i + p, in ? fi_f : -1.0f);
            __stcs(out_j + p, in ? fj_f : -1.0f);
            __stcs(out_d + p, in ? d    :  0.0f);
            float* rb = out_r + 3 * p;
            __stcs(rb + 0, in ? dx : 0.0f);
            __stcs(rb + 1, in ? dy : 0.0f);
            __stcs(rb + 2, in ? dz : 0.0f);
        }

        fast_ptr += fast_stride;
    }
}

extern "C" void kernel_launch(void* const* d_in, const int* in_sizes, int n_in,
                              void* d_out, int out_size)
{
    const float* pos   = (const float*)d_in[0];
    const float* box   = (const float*)d_in[1];
    const int*   isper = (const int*)d_in[2];
    float*       out   = (float*)d_out;

    const int n = in_sizes[0] / 3;
    const int P = (int)((long long)n * (n - 1) / 2);   // 17,997,000 for n=6000

    const int pairs_per_block = BLOCK_THREADS * 4;     // 1024
    const int grid = (P + pairs_per_block - 1) / pairs_per_block;
    neighborlist_kernel<<<grid, BLOCK_THREADS>>>(pos, box, isper,
                                                 out,
                                                 out + P,
                                                 out + 2 * (size_t)P,
                                                 out + 3 * (size_t)P,
                                                 n, P);
}

// round 13
// speedup vs baseline: 1.0040x; 1.0040x over previous
#include <cuda_runtime.h>

// NeighborlistForInference: brute-force N^2 upper-triangular pair list.
//
// Output layout (fp32, 6*P elements, P = n(n-1)/2):
//   [0   ,  P) : i index per pair (-1 if out of cutoff)
//   [P   , 2P) : j index per pair (-1)
//   [2P  , 3P) : d_ij (0)
//   [3P  , 6P) : r_ij row-major [P,3] (0)
//
// Round-11 = R10 + fast-path issue surgery:
//  * warp-constant output (768B) written by ONE predicated st.global.cs.v8.f32
//    on lanes 0..23 (32B/lane, Blackwell 256-bit stores): lanes 0-3 -> i block,
//    4-7 -> j block, 8-11 -> d block, 12-23 -> r block. Pointer/value/stride
//    per lane hoisted to the prologue.
//  * (float)i / (float)j conversions moved into the rare slow path.
//  * hot-loop loads clamped (min(j, n-1)) instead of predicated; partial
//    iterations always take the guarded scalar path (full == false).
//  * mask via s <= 0x3E800001 == (IEEE sqrtf(s) <= 0.5f); slow path stores
//    bit-identical values to R6/R10 (rel_err 3e-8).

#ifndef NL_CUTOFF
#define NL_CUTOFF 0.5f
#endif

#define BLOCK_THREADS 256   // 8 warps * 128 pairs = 1024 pairs per block

__device__ __forceinline__ int tri_start(int i, int n) {
    return (i * (2 * n - i - 1)) >> 1;     // row start, max ~36M fits int32
}

__device__ __forceinline__ int tri_row(int p, int n) {
    const int a = 2 * n - 1;
    const int disc = a * a - 8 * p;
    int i = (int)(0.5f * ((float)a - sqrtf((float)disc)));
    if (i < 0) i = 0;
    if (i > n - 2) i = n - 2;
    while (p < tri_start(i, n)) --i;
    while (i < n - 2 && p >= tri_start(i + 1, n)) ++i;
    return i;
}

__global__ __launch_bounds__(BLOCK_THREADS)
void neighborlist_kernel(const float* __restrict__ pos,
                         const float* __restrict__ box,
                         const int*   __restrict__ is_periodic,
                         float* __restrict__ out_i,
                         float* __restrict__ out_j,
                         float* __restrict__ out_d,
                         float* __restrict__ out_r,
                         int n, int P)
{
    const int warp = (blockIdx.x * BLOCK_THREADS + threadIdx.x) >> 5;
    const int lane = threadIdx.x & 31;
    const int wb   = warp * 128;
    if (wb >= P) return;

    // ---- per-lane triangular index at first pair (clamped for tail lanes)
    int p  = wb + lane;
    const int pc = min(p, P - 1);
    int i  = tri_row(pc, n);
    int rs = tri_start(i, n);
    int j  = i + 1 + (pc - rs);

    const float Lx = box[0], Ly = box[4], Lz = box[8];
    const float hx = 0.5f * Lx, hy = 0.5f * Ly, hz = 0.5f * Lz;
    const int per = *is_periodic;

    // largest float s with fl(sqrt(s)) <= 0.5  (== cutoff^2 + 1 ulp)
    const float SMAX = __uint_as_float(0x3E800001u);

    float xi = pos[3 * i + 0], yi = pos[3 * i + 1], zi = pos[3 * i + 2];

    // ---- fast-path cooperative store plan: lanes 0..23, 32B (8 floats) each.
    //   lanes 0-3: i block   (wb + 8*lane)        stride 32 floats/iter
    //   lanes 4-7: j block                        stride 32
    //   lanes 8-11: d block                       stride 32
    //   lanes 12-23: r block (3*wb + 8*(lane-12)) stride 96
    float* fast_ptr;
    {
        float* sb = (lane < 4) ? out_i : (lane < 8) ? out_j
                  : (lane < 12) ? out_d : out_r;
        const int off = (lane < 12) ? (wb + 8 * (lane & 3))
                                    : (3 * wb + 8 * (lane - 12));
        fast_ptr = sb + off;
    }
    const int   fast_stride = (lane < 12) ? 32 : 96;
    const float fast_val    = (lane < 8) ? -1.0f : 0.0f;

    #pragma unroll
    for (int m = 0; m < 4; ++m) {
        const int pb = wb + 32 * m;
        if (pb >= P) break;
        if (m) {
            p += 32;
            j += 32;
            if (j >= n && p < P) {             // row crossing(s)
                do {
                    rs += n - 1 - i;
                    ++i;
                    j = i + 1 + (p - rs);
                } while (j >= n);
                xi = pos[3 * i + 0]; yi = pos[3 * i + 1]; zi = pos[3 * i + 2];
            }
        }

        // memory-safe load index (tail lanes may have walked past n-1)
        const int jc = min(j, n - 1);
        float dx = xi - pos[3 * jc + 0];
        float dy = yi - pos[3 * jc + 1];
        float dz = zi - pos[3 * jc + 2];
        if (per) {
            // exact minimum-image for r in (-L, L): t in (-L/2, 3L/2)
            float tx = dx + hx; tx = (tx >= Lx) ? tx - Lx : tx; tx = (tx < 0.0f) ? tx + Lx : tx; dx = tx - hx;
            float ty = dy + hy; ty = (ty >= Ly) ? ty - Ly : ty; ty = (ty < 0.0f) ? ty + Ly : ty; dy = ty - hy;
            float tz = dz + hz; tz = (tz >= Lz) ? tz - Lz : tz; tz = (tz < 0.0f) ? tz + Lz : tz; dz = tz - hz;
        }
        const float s  = dx * dx + dy * dy + dz * dz;   // same contraction as R6
        const bool  in = (s <= SMAX);                   // == (sqrtf(s) <= 0.5f)
        const bool  full = (pb + 32 <= P);

        if (full && !__any_sync(0xffffffffu, in)) {
            // all 32 pairs out of cutoff: one 256-bit store on lanes 0..23
            if (lane < 24) {
                asm volatile(
                    "st.global.cs.v8.f32 [%0], {%1,%2,%3,%4,%5,%6,%7,%8};"
                    :: "l"(fast_ptr),
                       "f"(fast_val), "f"(fast_val), "f"(fast_val), "f"(fast_val),
                       "f"(fast_val), "f"(fast_val), "f"(fast_val), "f"(fast_val)
                    : "memory");
            }
        } else if (p < P) {
            const float d    = sqrtf(s);        // IEEE; rare path
            const float fi_f = (float)i;
            const float fj_f = (float)j;
            __stcs(out_i + p, in ? fi_f : -1.0f);
            __stcs(out_j + p, in ? fj_f : -1.0f);
            __stcs(out_d + p, in ? d    :  0.0f);
            float* rb = out_r + 3 * p;
            __stcs(rb + 0, in ? dx : 0.0f);
            __stcs(rb + 1, in ? dy : 0.0f);
            __stcs(rb + 2, in ? dz : 0.0f);
        }

        fast_ptr += fast_stride;
    }
}

extern "C" void kernel_launch(void* const* d_in, const int* in_sizes, int n_in,
                              void* d_out, int out_size)
{
    const float* pos   = (const float*)d_in[0];
    const float* box   = (const float*)d_in[1];
    const int*   isper = (const int*)d_in[2];
    float*       out   = (float*)d_out;

    const int n = in_sizes[0] / 3;
    const int P = (int)((long long)n * (n - 1) / 2);   // 17,997,000 for n=6000

    const int pairs_per_block = BLOCK_THREADS * 4;     // 1024
    const int grid = (P + pairs_per_block - 1) / pairs_per_block;
    neighborlist_kernel<<<grid, BLOCK_THREADS>>>(pos, box, isper,
                                                 out,
                                                 out + P,
                                                 out + 2 * (size_t)P,
                                                 out + 3 * (size_t)P,
                                                 n, P);
}

// round 14
// speedup vs baseline: 1.0372x; 1.0331x over previous
#include <cuda_runtime.h>

// NeighborlistForInference: brute-force N^2 upper-triangular pair list.
//
// Output layout (fp32, 6*P elements, P = n(n-1)/2):
//   [0   ,  P) : i index per pair (-1 if out of cutoff)
//   [P   , 2P) : j index per pair (-1)
//   [2P  , 3P) : d_ij (0)
//   [3P  , 6P) : r_ij row-major [P,3] (0)
//
// Round-13 = R10 (61.5us champion) with issue-slot surgery:
//  * 256 pairs per warp (8 iters) -> prologue (triangular inversion) cost halved.
//  * warp vote uses a CONSERVATIVE cheap mask: m = min(|dx|, L-|dx|) per
//    component, s_cheap <= 0.2503. |s_cheap - s_exact| <= ~2e-5 near the
//    boundary, so no truly-in pair can be missed. Warps failing the vote
//    re-run the exact t-form wrap + exact mask (s <= 0x3E800001 ==
//    sqrtf(s) <= 0.5f) + IEEE sqrt -> stored bits identical to R6/R10.
//  * fast store: two predicated STG.128 on lanes 0..23 (R10 scheme, which
//    measured faster than the R11 v8 experiment).
//  * full warps run a bounds-check-free hot loop; the single partial warp
//    takes a guarded scalar loop.

#ifndef NL_CUTOFF
#define NL_CUTOFF 0.5f
#endif

#define BLOCK_THREADS  256
#define ITERS          8
#define PAIRS_PER_WARP (32 * ITERS)   // 256

__device__ __forceinline__ int tri_start(int i, int n) {
    return (i * (2 * n - i - 1)) >> 1;     // row start, max ~36M fits int32
}

__device__ __forceinline__ int tri_row(int p, int n) {
    const int a = 2 * n - 1;
    const int disc = a * a - 8 * p;
    int i = (int)(0.5f * ((float)a - sqrtf((float)disc)));
    if (i < 0) i = 0;
    if (i > n - 2) i = n - 2;
    while (p < tri_start(i, n)) --i;
    while (i < n - 2 && p >= tri_start(i + 1, n)) ++i;
    return i;
}

__global__ __launch_bounds__(BLOCK_THREADS)
void neighborlist_kernel(const float* __restrict__ pos,
                         const float* __restrict__ box,
                         const int*   __restrict__ is_periodic,
                         float* __restrict__ out_i,
                         float* __restrict__ out_j,
                         float* __restrict__ out_d,
                         float* __restrict__ out_r,
                         int n, int P)
{
    const int warp = (blockIdx.x * BLOCK_THREADS + threadIdx.x) >> 5;
    const int lane = threadIdx.x & 31;
    const int wb   = warp * PAIRS_PER_WARP;
    if (wb >= P) return;

    // ---- per-lane triangular index at first pair (clamped for tail lanes)
    int p  = wb + lane;
    const int pc = min(p, P - 1);
    int i  = tri_row(pc, n);
    int rs = tri_start(i, n);
    int j  = i + 1 + (pc - rs);

    const float Lx = box[0], Ly = box[4], Lz = box[8];
    const float hx = 0.5f * Lx, hy = 0.5f * Ly, hz = 0.5f * Lz;
    const int per = *is_periodic;

    // cheap-mask effective box lengths: +INF disables wrapping when per==0
    const float INFF = __int_as_float(0x7f800000);
    const float LxE = per ? Lx : INFF;
    const float LyE = per ? Ly : INFF;
    const float LzE = per ? Lz : INFF;

    // exact mask threshold: largest s with fl(sqrt(s)) <= 0.5
    const float SMAX   = __uint_as_float(0x3E800001u);
    const float SCHEAP = 0.2503f;          // SMAX + conservative margin

    float xi = pos[3 * i + 0], yi = pos[3 * i + 1], zi = pos[3 * i + 2];

    // ---- fast-path cooperative store plan (R10 scheme):
    // lanes 0-7 -> i block, 8-15 -> j block, 16-23 -> d block (16B each),
    // lanes 0-23 also cover the 384B r block (16B each).
    float* ijd_ptr;
    {
        float* sb = (lane < 8) ? out_i : (lane < 16) ? out_j : out_d;
        ijd_ptr = sb + wb + 4 * (lane & 7);
    }
    float* r_ptr = out_r + 3 * wb + 4 * lane;
    const float4 cval = (lane < 16) ? make_float4(-1.f, -1.f, -1.f, -1.f)
                                    : make_float4(0.f, 0.f, 0.f, 0.f);
    const float4 zero4 = make_float4(0.f, 0.f, 0.f, 0.f);
    const bool storer = (lane < 24);

    if (wb + PAIRS_PER_WARP <= P) {
        // ================= full warp: no bounds checks =================
        #pragma unroll
        for (int m = 0; m < ITERS; ++m) {
            if (m) {
                p += 32; j += 32;
                if (j >= n) {               // row crossing(s)
                    do {
                        rs += n - 1 - i;
                        ++i;
                        j = i + 1 + (p - rs);
                    } while (j >= n);
                    xi = pos[3 * i + 0]; yi = pos[3 * i + 1]; zi = pos[3 * i + 2];
                }
            }

            float dx = xi - pos[3 * j + 0];
            float dy = yi - pos[3 * j + 1];
            float dz = zi - pos[3 * j + 2];

            // conservative min-image magnitude (never under-counts a hit)
            const float ax = fabsf(dx), mx = fminf(ax, LxE - ax);
            const float ay = fabsf(dy), my = fminf(ay, LyE - ay);
            const float az = fabsf(dz), mz = fminf(az, LzE - az);
            const float sc = mx * mx + my * my + mz * mz;

            if (!__any_sync(0xffffffffu, sc <= SCHEAP)) {
                // all 32 pairs clearly out: constant outputs, 2 x STG.128
                if (storer) {
                    __stcs((float4*)ijd_ptr, cval);
                    __stcs((float4*)r_ptr,   zero4);
                }
            } else {
                // exact path (bit-identical to R6/R10)
                if (per) {
                    float tx = dx + hx; tx = (tx >= Lx) ? tx - Lx : tx; tx = (tx < 0.0f) ? tx + Lx : tx; dx = tx - hx;
                    float ty = dy + hy; ty = (ty >= Ly) ? ty - Ly : ty; ty = (ty < 0.0f) ? ty + Ly : ty; dy = ty - hy;
                    float tz = dz + hz; tz = (tz >= Lz) ? tz - Lz : tz; tz = (tz < 0.0f) ? tz + Lz : tz; dz = tz - hz;
                }
                const float s  = dx * dx + dy * dy + dz * dz;
                const bool  in = (s <= SMAX);     // == (sqrtf(s) <= 0.5f)
                const float d  = sqrtf(s);        // IEEE
                __stcs(out_i + p, in ? (float)i : -1.0f);
                __stcs(out_j + p, in ? (float)j : -1.0f);
                __stcs(out_d + p, in ? d        :  0.0f);
                float* rb = out_r + 3 * p;
                __stcs(rb + 0, in ? dx : 0.0f);
                __stcs(rb + 1, in ? dy : 0.0f);
                __stcs(rb + 2, in ? dz : 0.0f);
            }

            ijd_ptr += 32;                  // +128B per iteration
            r_ptr   += 96;                  // +384B per iteration
        }
    } else {
        // ============ partial (last) warp: guarded scalar loop ============
        #pragma unroll 1
        for (int m = 0; m < ITERS; ++m) {
            if (m) {
                p += 32; j += 32;
                if (j >= n && p < P) {
                    do {
                        rs += n - 1 - i;
                        ++i;
                        j = i + 1 + (p - rs);
                    } while (j >= n);
                    xi = pos[3 * i + 0]; yi = pos[3 * i + 1]; zi = pos[3 * i + 2];
                }
            }
            if (p < P) {
                float dx = xi - pos[3 * j + 0];
                float dy = yi - pos[3 * j + 1];
                float dz = zi - pos[3 * j + 2];
                if (per) {
                    float tx = dx + hx; tx = (tx >= Lx) ? tx - Lx : tx; tx = (tx < 0.0f) ? tx + Lx : tx; dx = tx - hx;
                    float ty = dy + hy; ty = (ty >= Ly) ? ty - Ly : ty; ty = (ty < 0.0f) ? ty + Ly : ty; dy = ty - hy;
                    float tz = dz + hz; tz = (tz >= Lz) ? tz - Lz : tz; tz = (tz < 0.0f) ? tz + Lz : tz; dz = tz - hz;
                }
                const float s  = dx * dx + dy * dy + dz * dz;
                const bool  in = (s <= SMAX);
                const float d  = sqrtf(s);
                __stcs(out_i + p, in ? (float)i : -1.0f);
                __stcs(out_j + p, in ? (float)j : -1.0f);
                __stcs(out_d + p, in ? d        :  0.0f);
                float* rb = out_r + 3 * p;
                __stcs(rb + 0, in ? dx : 0.0f);
                __stcs(rb + 1, in ? dy : 0.0f);
                __stcs(rb + 2, in ? dz : 0.0f);
            }
        }
    }
}

extern "C" void kernel_launch(void* const* d_in, const int* in_sizes, int n_in,
                              void* d_out, int out_size)
{
    const float* pos   = (const float*)d_in[0];
    const float* box   = (const float*)d_in[1];
    const int*   isper = (const int*)d_in[2];
    float*       out   = (float*)d_out;

    const int n = in_sizes[0] / 3;
    const int P = (int)((long long)n * (n - 1) / 2);   // 17,997,000 for n=6000

    const int pairs_per_block = (BLOCK_THREADS / 32) * PAIRS_PER_WARP;  // 2048
    const int grid = (P + pairs_per_block - 1) / pairs_per_block;
    neighborlist_kernel<<<grid, BLOCK_THREADS>>>(pos, box, isper,
                                                 out,
                                                 out + P,
                                                 out + 2 * (size_t)P,
                                                 out + 3 * (size_t)P,
                                                 n, P);
}